// round 5
// baseline (speedup 1.0000x reference)
#include <cuda_runtime.h>
#include <cuda_bf16.h>
#include <math.h>
#include <stdint.h>

#define BB   16
#define CC   64
#define NP   128
#define DD   128
#define HT   4
#define DH   32
#define HS   4
#define FF   128
#define DK   64
#define NTOK (BB*CC*NP)      // 131072
#define NSEQ (BB*CC)         // 1024
#define GAT_NEG -1e30f

// ---------------- scratch ----------------------------------------------------
__device__ float g_h[NTOK*DD];
__device__ float g_qkv[(size_t)NTOK*3*DD];
__device__ float g_o[NTOK*DD];
__device__ float g_x[NTOK*DD];
__device__ float g_ff[(size_t)NTOK*4*DD];
__device__ float g_Htemp[NTOK*DD];
__device__ float g_xh[(size_t)NTOK*HS*FF];
__device__ float g_Hs[NSEQ*DD];
__device__ float g_q2[NSEQ*DK];
__device__ float g_k2[NSEQ*DK];
__device__ float g_mask[BB*CC*CC];

// ---------------- helpers ----------------------------------------------------
__device__ __forceinline__ float to_tf32(float x) {
    asm("cvt.rna.tf32.f32 %0, %1;" : "=f"(x) : "f"(x));
    return x;
}
__device__ __forceinline__ void mma8(float c[4], const uint32_t a[4],
                                     uint32_t b0, uint32_t b1) {
    asm volatile(
        "mma.sync.aligned.m16n8k8.row.col.f32.tf32.tf32.f32 "
        "{%0,%1,%2,%3}, {%4,%5,%6,%7}, {%8,%9}, {%0,%1,%2,%3};"
        : "+f"(c[0]), "+f"(c[1]), "+f"(c[2]), "+f"(c[3])
        : "r"(a[0]), "r"(a[1]), "r"(a[2]), "r"(a[3]), "r"(b0), "r"(b1));
}

// ---------------- LayerNorm: warp per row (used for ln1 only) ----------------
__global__ void k_ln(const float* __restrict__ x,
                     const float* __restrict__ gw, const float* __restrict__ bw,
                     float* __restrict__ out)
{
    int row  = blockIdx.x * 8 + (threadIdx.x >> 5);
    int lane = threadIdx.x & 31;
    float4 v = ((const float4*)(x + (size_t)row * DD))[lane];
    float s = v.x + v.y + v.z + v.w;
    #pragma unroll
    for (int o = 16; o; o >>= 1) s += __shfl_xor_sync(0xffffffffu, s, o);
    float mean = s * (1.f/128.f);
    float dx = v.x-mean, dy = v.y-mean, dz = v.z-mean, dw = v.w-mean;
    float q = dx*dx + dy*dy + dz*dz + dw*dw;
    #pragma unroll
    for (int o = 16; o; o >>= 1) q += __shfl_xor_sync(0xffffffffu, q, o);
    float inv = rsqrtf(q * (1.f/128.f) + 1e-5f);
    float4 g4 = ((const float4*)gw)[lane];
    float4 b4 = ((const float4*)bw)[lane];
    float4 o4;
    o4.x = dx*inv*g4.x + b4.x;  o4.y = dy*inv*g4.y + b4.y;
    o4.z = dz*inv*g4.z + b4.z;  o4.w = dw*inv*g4.w + b4.w;
    ((float4*)(out + (size_t)row * DD))[lane] = o4;
}

// ---------------- tf32 tensor-core GEMM with optional fused row-LN epilogue --
// out = A@W^T + bias (+res) (+x0) ; if lng: also out2 = rowLN(v)*lng+lnb.
// LN mode requires gridDim.x==1 (N==128 -> CTA holds full rows).
#define TBM 128
#define TBN 128
#define TBK 32
#define TPAD 4
__global__ void k_mma(const float* __restrict__ A, const float* __restrict__ W,
                      const float* __restrict__ bias, const float* __restrict__ res,
                      const float* __restrict__ x0, float* __restrict__ out,
                      float* __restrict__ out2,
                      const float* __restrict__ lng, const float* __restrict__ lnb,
                      int M, int N, int K, int relu)
{
    __shared__ float As[TBM][TBK + TPAD];
    __shared__ float Bs[TBN][TBK + TPAD];
    __shared__ float red[128*8];
    int tid  = threadIdx.x;
    int warp = tid >> 5, lane = tid & 31;
    int wm = warp >> 1, wn = warp & 1;
    int g = lane >> 2, t = lane & 3;
    int m0 = blockIdx.y * TBM;
    int n0 = blockIdx.x * TBN;

    float acc[2][8][4] = {};

    for (int k0 = 0; k0 < K; k0 += TBK) {
        #pragma unroll
        for (int i = 0; i < 4; i++) {
            int idx = tid + i * 256;
            int r = idx >> 3, c4 = (idx & 7) << 2;
            float4 a4 = *(const float4*)(A + (size_t)(m0 + r) * K + k0 + c4);
            float4 w4 = *(const float4*)(W + (size_t)(n0 + r) * K + k0 + c4);
            *(float4*)&As[r][c4] = make_float4(to_tf32(a4.x), to_tf32(a4.y), to_tf32(a4.z), to_tf32(a4.w));
            *(float4*)&Bs[r][c4] = make_float4(to_tf32(w4.x), to_tf32(w4.y), to_tf32(w4.z), to_tf32(w4.w));
        }
        __syncthreads();
        #pragma unroll
        for (int kk = 0; kk < TBK; kk += 8) {
            uint32_t afrag[2][4];
            #pragma unroll
            for (int mi = 0; mi < 2; mi++) {
                int r = wm * 32 + mi * 16;
                afrag[mi][0] = __float_as_uint(As[r + g    ][kk + t    ]);
                afrag[mi][1] = __float_as_uint(As[r + g + 8][kk + t    ]);
                afrag[mi][2] = __float_as_uint(As[r + g    ][kk + t + 4]);
                afrag[mi][3] = __float_as_uint(As[r + g + 8][kk + t + 4]);
            }
            #pragma unroll
            for (int ni = 0; ni < 8; ni++) {
                int c = wn * 64 + ni * 8;
                uint32_t b0 = __float_as_uint(Bs[c + g][kk + t    ]);
                uint32_t b1 = __float_as_uint(Bs[c + g][kk + t + 4]);
                mma8(acc[0][ni], afrag[0], b0, b1);
                mma8(acc[1][ni], afrag[1], b0, b1);
            }
        }
        __syncthreads();
    }

    if (!lng) {
        #pragma unroll
        for (int mi = 0; mi < 2; mi++) {
            #pragma unroll
            for (int ni = 0; ni < 8; ni++) {
                int r = m0 + wm * 32 + mi * 16 + g;
                int c = n0 + wn * 64 + ni * 8 + 2 * t;
                float bv0 = bias ? bias[c]     : 0.f;
                float bv1 = bias ? bias[c + 1] : 0.f;
                #pragma unroll
                for (int half = 0; half < 2; half++) {
                    int row = r + half * 8;
                    float v0 = acc[mi][ni][half*2 + 0] + bv0;
                    float v1 = acc[mi][ni][half*2 + 1] + bv1;
                    if (relu) { v0 = fmaxf(v0, 0.f); v1 = fmaxf(v1, 0.f); }
                    if (res) {
                        const float2 rr = *(const float2*)(res + (size_t)row * N + c);
                        v0 += rr.x; v1 += rr.y;
                    }
                    *(float2*)(out + (size_t)row * N + c) = make_float2(v0, v1);
                }
            }
        }
        return;
    }

    // ---- fused LN epilogue (N==128, full rows in CTA) ----
    // pass 1: row sums
    float ps[2][2] = {};
    #pragma unroll
    for (int mi = 0; mi < 2; mi++)
        #pragma unroll
        for (int ni = 0; ni < 8; ni++) {
            int c = wn * 64 + ni * 8 + 2 * t;
            float bv0 = bias[c], bv1 = bias[c + 1];
            #pragma unroll
            for (int half = 0; half < 2; half++) {
                int row = m0 + wm * 32 + mi * 16 + g + half * 8;
                float v0 = acc[mi][ni][half*2 + 0] + bv0;
                float v1 = acc[mi][ni][half*2 + 1] + bv1;
                if (res) { float2 rr = *(const float2*)(res + (size_t)row * 128 + c); v0 += rr.x; v1 += rr.y; }
                if (x0)  { float2 rr = *(const float2*)(x0  + (size_t)row * 128 + c); v0 += rr.x; v1 += rr.y; }
                ps[mi][half] += v0 + v1;
            }
        }
    #pragma unroll
    for (int mi = 0; mi < 2; mi++)
        #pragma unroll
        for (int half = 0; half < 2; half++)
            red[(wm*32 + mi*16 + g + half*8)*8 + wn*4 + t] = ps[mi][half];
    __syncthreads();
    float mean[2][2];
    #pragma unroll
    for (int mi = 0; mi < 2; mi++)
        #pragma unroll
        for (int half = 0; half < 2; half++) {
            int r = wm*32 + mi*16 + g + half*8;
            float s = 0.f;
            #pragma unroll
            for (int j = 0; j < 8; j++) s += red[r*8 + j];
            mean[mi][half] = s * (1.f/128.f);
        }
    __syncthreads();
    // pass 2: row sum of squares
    float pq[2][2] = {};
    #pragma unroll
    for (int mi = 0; mi < 2; mi++)
        #pragma unroll
        for (int ni = 0; ni < 8; ni++) {
            int c = wn * 64 + ni * 8 + 2 * t;
            float bv0 = bias[c], bv1 = bias[c + 1];
            #pragma unroll
            for (int half = 0; half < 2; half++) {
                int row = m0 + wm * 32 + mi * 16 + g + half * 8;
                float v0 = acc[mi][ni][half*2 + 0] + bv0;
                float v1 = acc[mi][ni][half*2 + 1] + bv1;
                if (res) { float2 rr = *(const float2*)(res + (size_t)row * 128 + c); v0 += rr.x; v1 += rr.y; }
                if (x0)  { float2 rr = *(const float2*)(x0  + (size_t)row * 128 + c); v0 += rr.x; v1 += rr.y; }
                float d0 = v0 - mean[mi][half], d1 = v1 - mean[mi][half];
                pq[mi][half] += d0*d0 + d1*d1;
            }
        }
    #pragma unroll
    for (int mi = 0; mi < 2; mi++)
        #pragma unroll
        for (int half = 0; half < 2; half++)
            red[(wm*32 + mi*16 + g + half*8)*8 + wn*4 + t] = pq[mi][half];
    __syncthreads();
    float rinv[2][2];
    #pragma unroll
    for (int mi = 0; mi < 2; mi++)
        #pragma unroll
        for (int half = 0; half < 2; half++) {
            int r = wm*32 + mi*16 + g + half*8;
            float s = 0.f;
            #pragma unroll
            for (int j = 0; j < 8; j++) s += red[r*8 + j];
            rinv[mi][half] = rsqrtf(s * (1.f/128.f) + 1e-5f);
        }
    // pass 3: write
    #pragma unroll
    for (int mi = 0; mi < 2; mi++)
        #pragma unroll
        for (int ni = 0; ni < 8; ni++) {
            int c = wn * 64 + ni * 8 + 2 * t;
            float bv0 = bias[c], bv1 = bias[c + 1];
            float lg0 = lng[c], lg1 = lng[c+1];
            float lb0 = lnb[c], lb1 = lnb[c+1];
            #pragma unroll
            for (int half = 0; half < 2; half++) {
                int row = m0 + wm * 32 + mi * 16 + g + half * 8;
                float v0 = acc[mi][ni][half*2 + 0] + bv0;
                float v1 = acc[mi][ni][half*2 + 1] + bv1;
                if (res) { float2 rr = *(const float2*)(res + (size_t)row * 128 + c); v0 += rr.x; v1 += rr.y; }
                if (x0)  { float2 rr = *(const float2*)(x0  + (size_t)row * 128 + c); v0 += rr.x; v1 += rr.y; }
                if (out) *(float2*)(out + (size_t)row * 128 + c) = make_float2(v0, v1);
                float m = mean[mi][half], iv = rinv[mi][half];
                float o0 = (v0 - m)*iv*lg0 + lb0;
                float o1 = (v1 - m)*iv*lg1 + lb1;
                *(float2*)(out2 + (size_t)row * 128 + c) = make_float2(o0, o1);
            }
        }
}

// ---------------- small SIMT GEMM (q2/k2) ------------------------------------
#define BM 64
#define BN 64
#define BK 16
__global__ void k_gemm(const float* __restrict__ A, const float* __restrict__ W,
                       const float* __restrict__ bias, float* __restrict__ out,
                       int M, int N, int K)
{
    __shared__ float As[BK][BM];
    __shared__ float Bs[BK][BN];
    int tid = threadIdx.x;
    int tx = tid & 15, ty = tid >> 4;
    int m0 = blockIdx.y * BM, n0 = blockIdx.x * BN;
    int lr = tid >> 2;
    int lk = (tid & 3) * 4;
    float acc[4][4] = {};
    for (int k0 = 0; k0 < K; k0 += BK) {
        float4 a4 = *(const float4*)(A + (size_t)(m0 + lr) * K + k0 + lk);
        float4 b4 = *(const float4*)(W + (size_t)(n0 + lr) * K + k0 + lk);
        As[lk+0][lr] = a4.x; As[lk+1][lr] = a4.y; As[lk+2][lr] = a4.z; As[lk+3][lr] = a4.w;
        Bs[lk+0][lr] = b4.x; Bs[lk+1][lr] = b4.y; Bs[lk+2][lr] = b4.z; Bs[lk+3][lr] = b4.w;
        __syncthreads();
        #pragma unroll
        for (int k = 0; k < BK; k++) {
            float4 ra = *(const float4*)&As[k][ty*4];
            float4 rb = *(const float4*)&Bs[k][tx*4];
            float av[4] = {ra.x, ra.y, ra.z, ra.w};
            float bv[4] = {rb.x, rb.y, rb.z, rb.w};
            #pragma unroll
            for (int i = 0; i < 4; i++)
                #pragma unroll
                for (int j = 0; j < 4; j++)
                    acc[i][j] += av[i] * bv[j];
        }
        __syncthreads();
    }
    #pragma unroll
    for (int i = 0; i < 4; i++) {
        int m = m0 + ty*4 + i;
        #pragma unroll
        for (int j = 0; j < 4; j++) {
            int n = n0 + tx*4 + j;
            out[(size_t)m * N + n] = acc[i][j] + bias[n];
        }
    }
}

// ============== tensor-core attention (R4-proven) ============================
#define AQS 36
#define APS 132
__global__ void __launch_bounds__(128)
k_attn_mma()
{
    extern __shared__ float sm[];
    float* U  = sm;
    float* VT = sm + 128*APS;
    float* Qs = U;
    float* Ks = U + 128*AQS;
    float* Ps = U;

    int n = blockIdx.x >> 2, h = blockIdx.x & 3;
    int tid = threadIdx.x;
    int warp = tid >> 5, lane = tid & 31;
    int g = lane >> 2, t = lane & 3;
    int m0 = warp * 32;
    const float* base = g_qkv + (size_t)n * NP * 3 * DD;

    for (int idx = tid; idx < NP*DH; idx += 128) {
        int j = idx >> 5, d = idx & 31;
        Qs[j*AQS + d]  = to_tf32(base[j*384 +       h*32 + d]);
        Ks[j*AQS + d]  = to_tf32(base[j*384 + 128 + h*32 + d]);
        VT[d*APS + j]  = to_tf32(base[j*384 + 256 + h*32 + d]);
    }
    __syncthreads();

    float s[2][16][4] = {};
    #pragma unroll
    for (int kk = 0; kk < 32; kk += 8) {
        uint32_t afrag[2][4];
        #pragma unroll
        for (int mi = 0; mi < 2; mi++) {
            int r = m0 + mi * 16;
            afrag[mi][0] = __float_as_uint(Qs[(r + g    )*AQS + kk + t    ]);
            afrag[mi][1] = __float_as_uint(Qs[(r + g + 8)*AQS + kk + t    ]);
            afrag[mi][2] = __float_as_uint(Qs[(r + g    )*AQS + kk + t + 4]);
            afrag[mi][3] = __float_as_uint(Qs[(r + g + 8)*AQS + kk + t + 4]);
        }
        #pragma unroll
        for (int ni = 0; ni < 16; ni++) {
            int c = ni * 8;
            uint32_t b0 = __float_as_uint(Ks[(c + g)*AQS + kk + t    ]);
            uint32_t b1 = __float_as_uint(Ks[(c + g)*AQS + kk + t + 4]);
            mma8(s[0][ni], afrag[0], b0, b1);
            mma8(s[1][ni], afrag[1], b0, b1);
        }
    }
    __syncthreads();

    const float scale = 0.17677669529663687f;
    float mx[2][2] = {{-INFINITY,-INFINITY},{-INFINITY,-INFINITY}};
    #pragma unroll
    for (int mi = 0; mi < 2; mi++)
        #pragma unroll
        for (int ni = 0; ni < 16; ni++) {
            #pragma unroll
            for (int q = 0; q < 4; q++) s[mi][ni][q] *= scale;
            mx[mi][0] = fmaxf(mx[mi][0], fmaxf(s[mi][ni][0], s[mi][ni][1]));
            mx[mi][1] = fmaxf(mx[mi][1], fmaxf(s[mi][ni][2], s[mi][ni][3]));
        }
    #pragma unroll
    for (int mi = 0; mi < 2; mi++)
        #pragma unroll
        for (int hf = 0; hf < 2; hf++) {
            mx[mi][hf] = fmaxf(mx[mi][hf], __shfl_xor_sync(0xffffffffu, mx[mi][hf], 1));
            mx[mi][hf] = fmaxf(mx[mi][hf], __shfl_xor_sync(0xffffffffu, mx[mi][hf], 2));
        }
    float sum[2][2] = {};
    #pragma unroll
    for (int mi = 0; mi < 2; mi++)
        #pragma unroll
        for (int ni = 0; ni < 16; ni++) {
            s[mi][ni][0] = expf(s[mi][ni][0] - mx[mi][0]);
            s[mi][ni][1] = expf(s[mi][ni][1] - mx[mi][0]);
            s[mi][ni][2] = expf(s[mi][ni][2] - mx[mi][1]);
            s[mi][ni][3] = expf(s[mi][ni][3] - mx[mi][1]);
            sum[mi][0] += s[mi][ni][0] + s[mi][ni][1];
            sum[mi][1] += s[mi][ni][2] + s[mi][ni][3];
        }
    float inv[2][2];
    #pragma unroll
    for (int mi = 0; mi < 2; mi++)
        #pragma unroll
        for (int hf = 0; hf < 2; hf++) {
            float ss = sum[mi][hf];
            ss += __shfl_xor_sync(0xffffffffu, ss, 1);
            ss += __shfl_xor_sync(0xffffffffu, ss, 2);
            inv[mi][hf] = 1.f / ss;
        }

    #pragma unroll
    for (int mi = 0; mi < 2; mi++) {
        int r0 = m0 + mi * 16 + g;
        #pragma unroll
        for (int ni = 0; ni < 16; ni++) {
            int c = ni * 8 + 2 * t;
            Ps[ r0      *APS + c    ] = to_tf32(s[mi][ni][0]);
            Ps[ r0      *APS + c + 1] = to_tf32(s[mi][ni][1]);
            Ps[(r0 + 8) *APS + c    ] = to_tf32(s[mi][ni][2]);
            Ps[(r0 + 8) *APS + c + 1] = to_tf32(s[mi][ni][3]);
        }
    }
    __syncwarp();

    float o[2][4][4] = {};
    #pragma unroll
    for (int kk = 0; kk < 128; kk += 8) {
        uint32_t afrag[2][4];
        #pragma unroll
        for (int mi = 0; mi < 2; mi++) {
            int r = m0 + mi * 16;
            afrag[mi][0] = __float_as_uint(Ps[(r + g    )*APS + kk + t    ]);
            afrag[mi][1] = __float_as_uint(Ps[(r + g + 8)*APS + kk + t    ]);
            afrag[mi][2] = __float_as_uint(Ps[(r + g    )*APS + kk + t + 4]);
            afrag[mi][3] = __float_as_uint(Ps[(r + g + 8)*APS + kk + t + 4]);
        }
        #pragma unroll
        for (int ni = 0; ni < 4; ni++) {
            int c = ni * 8;
            uint32_t b0 = __float_as_uint(VT[(c + g)*APS + kk + t    ]);
            uint32_t b1 = __float_as_uint(VT[(c + g)*APS + kk + t + 4]);
            mma8(o[0][ni], afrag[0], b0, b1);
            mma8(o[1][ni], afrag[1], b0, b1);
        }
    }

    #pragma unroll
    for (int mi = 0; mi < 2; mi++) {
        int r0 = m0 + mi * 16 + g;
        #pragma unroll
        for (int ni = 0; ni < 4; ni++) {
            int d = ni * 8 + 2 * t;
            *(float2*)(g_o + (size_t)(n*NP + r0    )*DD + h*32 + d) =
                make_float2(o[mi][ni][0]*inv[mi][0], o[mi][ni][1]*inv[mi][0]);
            *(float2*)(g_o + (size_t)(n*NP + r0 + 8)*DD + h*32 + d) =
                make_float2(o[mi][ni][2]*inv[mi][1], o[mi][ni][3]*inv[mi][1]);
        }
    }
}

// ---------------- mean over Np -----------------------------------------------
__global__ void k_mean()
{
    int n = blockIdx.x, d = threadIdx.x;
    float s = 0.f;
    for (int p = 0; p < NP; p++) s += g_Htemp[((size_t)n*NP + p)*DD + d];
    g_Hs[n*DD + d] = s * (1.f/128.f);
}

// ---------------- graph adjacency --------------------------------------------
__global__ void k_graph(const float* __restrict__ adj)
{
    __shared__ float k2s[CC*DK];
    __shared__ float Amat[CC*65];
    int b = blockIdx.x, c = threadIdx.x;
    for (int idx = c; idx < CC*DK; idx += 64) k2s[idx] = g_k2[(size_t)b*CC*DK + idx];
    __syncthreads();
    float qreg[DK];
    #pragma unroll
    for (int d = 0; d < DK; d++) qreg[d] = g_q2[(size_t)b*CC*DK + c*DK + d];
    for (int e = 0; e < CC; e++) {
        float a = 0.f;
        #pragma unroll
        for (int d = 0; d < DK; d++) a += qreg[d] * k2s[e*DK + d];
        Amat[c*65 + e] = tanhf(a * 0.125f) + adj[c*CC + e];
    }
    for (int e = 0; e < CC; e++) g_mask[(size_t)b*CC*CC + c*CC + e] = 0.f;
    for (int kk = 0; kk < 8; kk++) {
        float best = -INFINITY; int bi = 0;
        for (int e = 0; e < CC; e++) {
            float v = Amat[c*65 + e];
            if (v > best) { best = v; bi = e; }
        }
        if (bi != c && best != 0.f) g_mask[(size_t)b*CC*CC + c*CC + bi] = 1.f;
        Amat[c*65 + bi] = -INFINITY;
    }
}

// ============== GAT v2: tensor-core aggregation + fused snorm LN =============
// smem: U = max(XhT[128][68], Os[64][132]) ; Awt[64][68] ; Asv[64] ; Adv[64]
#define XST 68
#define AST 68
#define OST 132
#define GU  8704          // 128*68
__global__ void __launch_bounds__(256)
k_gat(const float* __restrict__ attsrc, const float* __restrict__ attdst,
      const float* __restrict__ gbias, const float* __restrict__ sg,
      const float* __restrict__ sb, float* __restrict__ out)
{
    extern __shared__ float sm[];
    float* U   = sm;                 // XhT / Os union (8704 floats)
    float* Awt = sm + GU;            // 64*68 = 4352
    float* Asv = sm + GU + 4352;     // 64
    float* Adv = sm + GU + 4416;     // 64
    float* XhT = U;
    float* Os  = U;

    int b = blockIdx.x >> 7, p = blockIdx.x & 127;
    int tid = threadIdx.x, w = tid >> 5, lane = tid & 31;
    int wm = w >> 2, wn = w & 3;
    int g = lane >> 2, t4 = lane & 3;

    // hoist mask loads (same for all heads)
    float mr0[8], mr1[8];
    #pragma unroll
    for (int i = 0; i < 8; i++) {
        int t = w*8 + i;
        mr0[i] = g_mask[(size_t)b*CC*CC + lane*CC + t];
        mr1[i] = g_mask[(size_t)b*CC*CC + (lane+32)*CC + t];
    }

    float acc[2][4][4] = {};
    for (int h = 0; h < HS; h++) {
        __syncthreads();
        // load XhT[f][s] (gmem coalesced over f)
        for (int idx = tid; idx < CC*FF; idx += 256) {
            int s = idx >> 7, f = idx & 127;
            XhT[f*XST + s] = to_tf32(g_xh[(size_t)(((b*CC + s)*NP + p))*(HS*FF) + h*FF + f]);
        }
        __syncthreads();

        // asrc/adst per source s
        for (int s = w; s < CC; s += 8) {
            float vs = 0.f, vd = 0.f;
            #pragma unroll
            for (int j = 0; j < 4; j++) {
                int f = lane + 32*j;
                float xv = XhT[f*XST + s];
                vs += xv * attsrc[h*FF + f];
                vd += xv * attdst[h*FF + f];
            }
            #pragma unroll
            for (int o = 16; o; o >>= 1) {
                vs += __shfl_xor_sync(0xffffffffu, vs, o);
                vd += __shfl_xor_sync(0xffffffffu, vd, o);
            }
            if (lane == 0) { Asv[s] = vs; Adv[s] = vd; }
        }
        __syncthreads();

        // masked softmax -> Awt[t][s] (transposed, tf32)
        #pragma unroll
        for (int i = 0; i < 8; i++) {
            int t = w*8 + i;
            float adt = Adv[t];
            float e0 = Asv[lane]      + adt; e0 = e0 > 0.f ? e0 : 0.2f*e0;
            float e1 = Asv[lane + 32] + adt; e1 = e1 > 0.f ? e1 : 0.2f*e1;
            float me = fmaxf(mr0[i] > 0.5f ? e0 : GAT_NEG, mr1[i] > 0.5f ? e1 : GAT_NEG);
            #pragma unroll
            for (int o = 16; o; o >>= 1) me = fmaxf(me, __shfl_xor_sync(0xffffffffu, me, o));
            float w0 = (mr0[i] > 0.5f) ? expf(e0 - me) : 0.f;
            float w1 = (mr1[i] > 0.5f) ? expf(e1 - me) : 0.f;
            float ws = w0 + w1;
            #pragma unroll
            for (int o = 16; o; o >>= 1) ws += __shfl_xor_sync(0xffffffffu, ws, o);
            float inv = ws > 0.f ? 1.f / ws : 0.f;
            Awt[t*AST + lane]      = to_tf32(w0 * inv);
            Awt[t*AST + lane + 32] = to_tf32(w1 * inv);
        }
        __syncthreads();

        // mma aggregation: C[t][f] += sum_s Awt[t][s] * XhT[f][s]
        #pragma unroll
        for (int kk = 0; kk < CC; kk += 8) {
            uint32_t afrag[2][4];
            #pragma unroll
            for (int mi = 0; mi < 2; mi++) {
                int r = wm * 32 + mi * 16;
                afrag[mi][0] = __float_as_uint(Awt[(r + g    )*AST + kk + t4    ]);
                afrag[mi][1] = __float_as_uint(Awt[(r + g + 8)*AST + kk + t4    ]);
                afrag[mi][2] = __float_as_uint(Awt[(r + g    )*AST + kk + t4 + 4]);
                afrag[mi][3] = __float_as_uint(Awt[(r + g + 8)*AST + kk + t4 + 4]);
            }
            #pragma unroll
            for (int ni = 0; ni < 4; ni++) {
                int c = wn * 32 + ni * 8;
                uint32_t b0 = __float_as_uint(XhT[(c + g)*XST + kk + t4    ]);
                uint32_t b1 = __float_as_uint(XhT[(c + g)*XST + kk + t4 + 4]);
                mma8(acc[0][ni], afrag[0], b0, b1);
                mma8(acc[1][ni], afrag[1], b0, b1);
            }
        }
    }

    // ---- epilogue: Os = Htemp + gbias (coalesced), += acc/4, then snorm LN ----
    __syncthreads();
    for (int idx = tid; idx < CC*DD; idx += 256) {
        int r = idx >> 7, f = idx & 127;
        Os[r*OST + f] = g_Htemp[(((size_t)(b*CC + r))*NP + p)*DD + f] + gbias[f];
    }
    __syncthreads();
    #pragma unroll
    for (int mi = 0; mi < 2; mi++)
        #pragma unroll
        for (int ni = 0; ni < 4; ni++) {
            int r = wm*32 + mi*16 + g;
            int c = wn*32 + ni*8 + 2*t4;
            #pragma unroll
            for (int half = 0; half < 2; half++) {
                int row = r + half*8;
                Os[row*OST + c    ] += acc[mi][ni][half*2 + 0] * 0.25f;
                Os[row*OST + c + 1] += acc[mi][ni][half*2 + 1] * 0.25f;
            }
        }
    __syncthreads();
    {
        float4 g4 = ((const float4*)sg)[lane];
        float4 b4 = ((const float4*)sb)[lane];
        for (int r = w; r < CC; r += 8) {
            float4 v = *(float4*)&Os[r*OST + lane*4];
            float s1 = v.x + v.y + v.z + v.w;
            #pragma unroll
            for (int o = 16; o; o >>= 1) s1 += __shfl_xor_sync(0xffffffffu, s1, o);
            float mean = s1 * (1.f/128.f);
            float dx=v.x-mean, dy=v.y-mean, dz=v.z-mean, dw=v.w-mean;
            float q = dx*dx+dy*dy+dz*dz+dw*dw;
            #pragma unroll
            for (int o = 16; o; o >>= 1) q += __shfl_xor_sync(0xffffffffu, q, o);
            float inv = rsqrtf(q * (1.f/128.f) + 1e-5f);
            float4 ov;
            ov.x = dx*inv*g4.x + b4.x; ov.y = dy*inv*g4.y + b4.y;
            ov.z = dz*inv*g4.z + b4.z; ov.w = dw*inv*g4.w + b4.w;
            ((float4*)(out + (((size_t)(b*CC + r))*NP + p)*DD))[lane] = ov;
        }
    }
}

// ---------------- host launch -------------------------------------------------
extern "C" void kernel_launch(void* const* d_in, const int* in_sizes, int n_in,
                              void* d_out, int out_size)
{
    const float* H_in      = (const float*)d_in[0];
    const float* static_adj= (const float*)d_in[1];
    const float* attn_in_w = (const float*)d_in[2];
    const float* attn_in_b = (const float*)d_in[3];
    const float* attn_out_w= (const float*)d_in[4];
    const float* attn_out_b= (const float*)d_in[5];
    const float* ln1_g     = (const float*)d_in[6];
    const float* ln1_b     = (const float*)d_in[7];
    const float* ln2_g     = (const float*)d_in[8];
    const float* ln2_b     = (const float*)d_in[9];
    const float* ff1_w     = (const float*)d_in[10];
    const float* ff1_b     = (const float*)d_in[11];
    const float* ff2_w     = (const float*)d_in[12];
    const float* ff2_b     = (const float*)d_in[13];
    const float* tnorm_g   = (const float*)d_in[14];
    const float* tnorm_b   = (const float*)d_in[15];
    const float* q_w       = (const float*)d_in[16];
    const float* q_b       = (const float*)d_in[17];
    const float* k_w       = (const float*)d_in[18];
    const float* k_b       = (const float*)d_in[19];
    const float* gat_w     = (const float*)d_in[20];
    const float* gat_att_src = (const float*)d_in[21];
    const float* gat_att_dst = (const float*)d_in[22];
    const float* gat_bias  = (const float*)d_in[23];
    const float* snorm_g   = (const float*)d_in[24];
    const float* snorm_b   = (const float*)d_in[25];

    float *h_, *qkv_, *o_, *x_, *ff_, *Htemp_, *xh_, *Hs_, *q2_, *k2_;
    cudaGetSymbolAddress((void**)&h_,     g_h);
    cudaGetSymbolAddress((void**)&qkv_,   g_qkv);
    cudaGetSymbolAddress((void**)&o_,     g_o);
    cudaGetSymbolAddress((void**)&x_,     g_x);
    cudaGetSymbolAddress((void**)&ff_,    g_ff);
    cudaGetSymbolAddress((void**)&Htemp_, g_Htemp);
    cudaGetSymbolAddress((void**)&xh_,    g_xh);
    cudaGetSymbolAddress((void**)&Hs_,    g_Hs);
    cudaGetSymbolAddress((void**)&q2_,    g_q2);
    cudaGetSymbolAddress((void**)&k2_,    g_k2);

    const int attn_smem = (128*APS + 32*APS) * 4;      // 84480
    const int gat_smem  = (GU + 4352 + 128) * 4;       // 52736
    cudaFuncSetAttribute(k_attn_mma, cudaFuncAttributeMaxDynamicSharedMemorySize, attn_smem);
    cudaFuncSetAttribute(k_gat,  cudaFuncAttributeMaxDynamicSharedMemorySize, gat_smem);

    // 1) h = ln1(x0)
    k_ln<<<NTOK/8, 256>>>(H_in, ln1_g, ln1_b, h_);
    // 2) qkv = h @ Wqkv^T + b
    k_mma<<<dim3(3, NTOK/TBM), 256>>>(h_, attn_in_w, attn_in_b, nullptr, nullptr,
                                      qkv_, nullptr, nullptr, nullptr, NTOK, 384, 128, 0);
    // 3) temporal attention
    k_attn_mma<<<NSEQ*HT, 128, attn_smem>>>();
    // 4) x1 = x0 + o@Wout^T + b ; h = ln2(x1)   (fused)
    k_mma<<<dim3(1, NTOK/TBM), 256>>>(o_, attn_out_w, attn_out_b, H_in, nullptr,
                                      x_, h_, ln2_g, ln2_b, NTOK, 128, 128, 0);
    // 5) ff = relu(h @ W1^T + b1)
    k_mma<<<dim3(4, NTOK/TBM), 256>>>(h_, ff1_w, ff1_b, nullptr, nullptr,
                                      ff_, nullptr, nullptr, nullptr, NTOK, 512, 128, 1);
    // 6) Htemp = tnorm(x0 + x1 + ff@W2^T + b2)   (fused, x2 never materialized)
    k_mma<<<dim3(1, NTOK/TBM), 256>>>(ff_, ff2_w, ff2_b, x_, H_in,
                                      nullptr, Htemp_, tnorm_g, tnorm_b, NTOK, 128, 512, 0);
    // 7) xh = H_temp @ gat_w^T
    k_mma<<<dim3(4, NTOK/TBM), 256>>>(Htemp_, gat_w, nullptr, nullptr, nullptr,
                                      xh_, nullptr, nullptr, nullptr, NTOK, 512, 128, 0);
    // 8) Hs = mean_p(H_temp)
    k_mean<<<NSEQ, 128>>>();
    // 9) q2, k2
    k_gemm<<<dim3(1, NSEQ/BM), 256>>>(Hs_, q_w, q_b, q2_, NSEQ, 64, 128);
    k_gemm<<<dim3(1, NSEQ/BM), 256>>>(Hs_, k_w, k_b, k2_, NSEQ, 64, 128);
    // 10) adjacency / top-k / mask
    k_graph<<<BB, 64>>>(static_adj);
    // 11) GAT v2 (tensor cores) + snorm LN -> output
    k_gat<<<BB*NP, 256, gat_smem>>>(gat_att_src, gat_att_dst, gat_bias,
                                    snorm_g, snorm_b, (float*)d_out);
}

// round 6
// speedup vs baseline: 1.1770x; 1.1770x over previous
#include <cuda_runtime.h>
#include <cuda_bf16.h>
#include <math.h>
#include <stdint.h>

#define BB   16
#define CC   64
#define NP   128
#define DD   128
#define HT   4
#define DH   32
#define HS   4
#define FF   128
#define DK   64
#define NTOK (BB*CC*NP)      // 131072
#define NSEQ (BB*CC)         // 1024
#define GAT_NEG -1e30f

// ---------------- scratch ----------------------------------------------------
__device__ float g_h[NTOK*DD];
__device__ float g_qkv[(size_t)NTOK*3*DD];
__device__ float g_o[NTOK*DD];
__device__ float g_x[NTOK*DD];
__device__ float g_ff[(size_t)NTOK*4*DD];
__device__ float g_Htemp[NTOK*DD];
__device__ float g_xh[(size_t)NTOK*HS*FF];
__device__ float g_Hs[NSEQ*DD];
__device__ float g_q2[NSEQ*DK];
__device__ float g_k2[NSEQ*DK];
__device__ float g_mask[BB*CC*CC];

// ---------------- helpers ----------------------------------------------------
__device__ __forceinline__ float to_tf32(float x) {
    asm("cvt.rna.tf32.f32 %0, %1;" : "=f"(x) : "f"(x));
    return x;
}
__device__ __forceinline__ void mma8(float c[4], const uint32_t a[4],
                                     uint32_t b0, uint32_t b1) {
    asm volatile(
        "mma.sync.aligned.m16n8k8.row.col.f32.tf32.tf32.f32 "
        "{%0,%1,%2,%3}, {%4,%5,%6,%7}, {%8,%9}, {%0,%1,%2,%3};"
        : "+f"(c[0]), "+f"(c[1]), "+f"(c[2]), "+f"(c[3])
        : "r"(a[0]), "r"(a[1]), "r"(a[2]), "r"(a[3]), "r"(b0), "r"(b1));
}

// ---------------- LayerNorm: warp per row, optional fused add ----------------
__global__ void k_ln(const float* __restrict__ x, const float* __restrict__ add,
                     const float* __restrict__ gw, const float* __restrict__ bw,
                     float* __restrict__ out)
{
    int row  = blockIdx.x * 8 + (threadIdx.x >> 5);
    int lane = threadIdx.x & 31;
    const float4* xp = (const float4*)(x + (size_t)row * DD);
    float4 v = xp[lane];
    if (add) {
        float4 a = ((const float4*)(add + (size_t)row * DD))[lane];
        v.x += a.x; v.y += a.y; v.z += a.z; v.w += a.w;
    }
    float s = v.x + v.y + v.z + v.w;
    #pragma unroll
    for (int o = 16; o; o >>= 1) s += __shfl_xor_sync(0xffffffffu, s, o);
    float mean = s * (1.f/128.f);
    float dx = v.x-mean, dy = v.y-mean, dz = v.z-mean, dw = v.w-mean;
    float q = dx*dx + dy*dy + dz*dz + dw*dw;
    #pragma unroll
    for (int o = 16; o; o >>= 1) q += __shfl_xor_sync(0xffffffffu, q, o);
    float inv = rsqrtf(q * (1.f/128.f) + 1e-5f);
    float4 g4 = ((const float4*)gw)[lane];
    float4 b4 = ((const float4*)bw)[lane];
    float4 o4;
    o4.x = dx*inv*g4.x + b4.x;  o4.y = dy*inv*g4.y + b4.y;
    o4.z = dz*inv*g4.z + b4.z;  o4.w = dw*inv*g4.w + b4.w;
    ((float4*)(out + (size_t)row * DD))[lane] = o4;
}

// ---------------- tf32 tensor-core GEMM (R2/R4-proven, 128 regs) -------------
#define TBM 128
#define TBN 128
#define TBK 32
#define TPAD 4
__global__ void k_mma(const float* __restrict__ A, const float* __restrict__ W,
                      const float* __restrict__ bias, const float* __restrict__ res,
                      float* __restrict__ out, int M, int N, int K, int relu)
{
    __shared__ float As[TBM][TBK + TPAD];
    __shared__ float Bs[TBN][TBK + TPAD];
    int tid  = threadIdx.x;
    int warp = tid >> 5, lane = tid & 31;
    int wm = warp >> 1, wn = warp & 1;
    int g = lane >> 2, t = lane & 3;
    int m0 = blockIdx.y * TBM;
    int n0 = blockIdx.x * TBN;

    float acc[2][8][4] = {};

    for (int k0 = 0; k0 < K; k0 += TBK) {
        #pragma unroll
        for (int i = 0; i < 4; i++) {
            int idx = tid + i * 256;
            int r = idx >> 3, c4 = (idx & 7) << 2;
            float4 a4 = *(const float4*)(A + (size_t)(m0 + r) * K + k0 + c4);
            float4 w4 = *(const float4*)(W + (size_t)(n0 + r) * K + k0 + c4);
            *(float4*)&As[r][c4] = make_float4(to_tf32(a4.x), to_tf32(a4.y), to_tf32(a4.z), to_tf32(a4.w));
            *(float4*)&Bs[r][c4] = make_float4(to_tf32(w4.x), to_tf32(w4.y), to_tf32(w4.z), to_tf32(w4.w));
        }
        __syncthreads();
        #pragma unroll
        for (int kk = 0; kk < TBK; kk += 8) {
            uint32_t afrag[2][4];
            #pragma unroll
            for (int mi = 0; mi < 2; mi++) {
                int r = wm * 32 + mi * 16;
                afrag[mi][0] = __float_as_uint(As[r + g    ][kk + t    ]);
                afrag[mi][1] = __float_as_uint(As[r + g + 8][kk + t    ]);
                afrag[mi][2] = __float_as_uint(As[r + g    ][kk + t + 4]);
                afrag[mi][3] = __float_as_uint(As[r + g + 8][kk + t + 4]);
            }
            #pragma unroll
            for (int ni = 0; ni < 8; ni++) {
                int c = wn * 64 + ni * 8;
                uint32_t b0 = __float_as_uint(Bs[c + g][kk + t    ]);
                uint32_t b1 = __float_as_uint(Bs[c + g][kk + t + 4]);
                mma8(acc[0][ni], afrag[0], b0, b1);
                mma8(acc[1][ni], afrag[1], b0, b1);
            }
        }
        __syncthreads();
    }

    #pragma unroll
    for (int mi = 0; mi < 2; mi++) {
        #pragma unroll
        for (int ni = 0; ni < 8; ni++) {
            int r = m0 + wm * 32 + mi * 16 + g;
            int c = n0 + wn * 64 + ni * 8 + 2 * t;
            float bv0 = bias ? bias[c]     : 0.f;
            float bv1 = bias ? bias[c + 1] : 0.f;
            #pragma unroll
            for (int half = 0; half < 2; half++) {
                int row = r + half * 8;
                float v0 = acc[mi][ni][half*2 + 0] + bv0;
                float v1 = acc[mi][ni][half*2 + 1] + bv1;
                if (relu) { v0 = fmaxf(v0, 0.f); v1 = fmaxf(v1, 0.f); }
                if (res) {
                    const float2 rr = *(const float2*)(res + (size_t)row * N + c);
                    v0 += rr.x; v1 += rr.y;
                }
                *(float2*)(out + (size_t)row * N + c) = make_float2(v0, v1);
            }
        }
    }
}

// ---------------- small SIMT GEMM (q2/k2) ------------------------------------
#define BM 64
#define BN 64
#define BK 16
__global__ void k_gemm(const float* __restrict__ A, const float* __restrict__ W,
                       const float* __restrict__ bias, float* __restrict__ out,
                       int M, int N, int K)
{
    __shared__ float As[BK][BM];
    __shared__ float Bs[BK][BN];
    int tid = threadIdx.x;
    int tx = tid & 15, ty = tid >> 4;
    int m0 = blockIdx.y * BM, n0 = blockIdx.x * BN;
    int lr = tid >> 2;
    int lk = (tid & 3) * 4;
    float acc[4][4] = {};
    for (int k0 = 0; k0 < K; k0 += BK) {
        float4 a4 = *(const float4*)(A + (size_t)(m0 + lr) * K + k0 + lk);
        float4 b4 = *(const float4*)(W + (size_t)(n0 + lr) * K + k0 + lk);
        As[lk+0][lr] = a4.x; As[lk+1][lr] = a4.y; As[lk+2][lr] = a4.z; As[lk+3][lr] = a4.w;
        Bs[lk+0][lr] = b4.x; Bs[lk+1][lr] = b4.y; Bs[lk+2][lr] = b4.z; Bs[lk+3][lr] = b4.w;
        __syncthreads();
        #pragma unroll
        for (int k = 0; k < BK; k++) {
            float4 ra = *(const float4*)&As[k][ty*4];
            float4 rb = *(const float4*)&Bs[k][tx*4];
            float av[4] = {ra.x, ra.y, ra.z, ra.w};
            float bv[4] = {rb.x, rb.y, rb.z, rb.w};
            #pragma unroll
            for (int i = 0; i < 4; i++)
                #pragma unroll
                for (int j = 0; j < 4; j++)
                    acc[i][j] += av[i] * bv[j];
        }
        __syncthreads();
    }
    #pragma unroll
    for (int i = 0; i < 4; i++) {
        int m = m0 + ty*4 + i;
        #pragma unroll
        for (int j = 0; j < 4; j++) {
            int n = n0 + tx*4 + j;
            out[(size_t)m * N + n] = acc[i][j] + bias[n];
        }
    }
}

// ============== tensor-core attention (R4-proven) ============================
#define AQS 36
#define APS 132
__global__ void __launch_bounds__(128)
k_attn_mma()
{
    extern __shared__ float sm[];
    float* U  = sm;
    float* VT = sm + 128*APS;
    float* Qs = U;
    float* Ks = U + 128*AQS;
    float* Ps = U;

    int n = blockIdx.x >> 2, h = blockIdx.x & 3;
    int tid = threadIdx.x;
    int warp = tid >> 5, lane = tid & 31;
    int g = lane >> 2, t = lane & 3;
    int m0 = warp * 32;
    const float* base = g_qkv + (size_t)n * NP * 3 * DD;

    for (int idx = tid; idx < NP*DH; idx += 128) {
        int j = idx >> 5, d = idx & 31;
        Qs[j*AQS + d]  = to_tf32(base[j*384 +       h*32 + d]);
        Ks[j*AQS + d]  = to_tf32(base[j*384 + 128 + h*32 + d]);
        VT[d*APS + j]  = to_tf32(base[j*384 + 256 + h*32 + d]);
    }
    __syncthreads();

    float s[2][16][4] = {};
    #pragma unroll
    for (int kk = 0; kk < 32; kk += 8) {
        uint32_t afrag[2][4];
        #pragma unroll
        for (int mi = 0; mi < 2; mi++) {
            int r = m0 + mi * 16;
            afrag[mi][0] = __float_as_uint(Qs[(r + g    )*AQS + kk + t    ]);
            afrag[mi][1] = __float_as_uint(Qs[(r + g + 8)*AQS + kk + t    ]);
            afrag[mi][2] = __float_as_uint(Qs[(r + g    )*AQS + kk + t + 4]);
            afrag[mi][3] = __float_as_uint(Qs[(r + g + 8)*AQS + kk + t + 4]);
        }
        #pragma unroll
        for (int ni = 0; ni < 16; ni++) {
            int c = ni * 8;
            uint32_t b0 = __float_as_uint(Ks[(c + g)*AQS + kk + t    ]);
            uint32_t b1 = __float_as_uint(Ks[(c + g)*AQS + kk + t + 4]);
            mma8(s[0][ni], afrag[0], b0, b1);
            mma8(s[1][ni], afrag[1], b0, b1);
        }
    }
    __syncthreads();

    const float scale = 0.17677669529663687f;
    float mx[2][2] = {{-INFINITY,-INFINITY},{-INFINITY,-INFINITY}};
    #pragma unroll
    for (int mi = 0; mi < 2; mi++)
        #pragma unroll
        for (int ni = 0; ni < 16; ni++) {
            #pragma unroll
            for (int q = 0; q < 4; q++) s[mi][ni][q] *= scale;
            mx[mi][0] = fmaxf(mx[mi][0], fmaxf(s[mi][ni][0], s[mi][ni][1]));
            mx[mi][1] = fmaxf(mx[mi][1], fmaxf(s[mi][ni][2], s[mi][ni][3]));
        }
    #pragma unroll
    for (int mi = 0; mi < 2; mi++)
        #pragma unroll
        for (int hf = 0; hf < 2; hf++) {
            mx[mi][hf] = fmaxf(mx[mi][hf], __shfl_xor_sync(0xffffffffu, mx[mi][hf], 1));
            mx[mi][hf] = fmaxf(mx[mi][hf], __shfl_xor_sync(0xffffffffu, mx[mi][hf], 2));
        }
    float sum[2][2] = {};
    #pragma unroll
    for (int mi = 0; mi < 2; mi++)
        #pragma unroll
        for (int ni = 0; ni < 16; ni++) {
            s[mi][ni][0] = expf(s[mi][ni][0] - mx[mi][0]);
            s[mi][ni][1] = expf(s[mi][ni][1] - mx[mi][0]);
            s[mi][ni][2] = expf(s[mi][ni][2] - mx[mi][1]);
            s[mi][ni][3] = expf(s[mi][ni][3] - mx[mi][1]);
            sum[mi][0] += s[mi][ni][0] + s[mi][ni][1];
            sum[mi][1] += s[mi][ni][2] + s[mi][ni][3];
        }
    float inv[2][2];
    #pragma unroll
    for (int mi = 0; mi < 2; mi++)
        #pragma unroll
        for (int hf = 0; hf < 2; hf++) {
            float ss = sum[mi][hf];
            ss += __shfl_xor_sync(0xffffffffu, ss, 1);
            ss += __shfl_xor_sync(0xffffffffu, ss, 2);
            inv[mi][hf] = 1.f / ss;
        }

    #pragma unroll
    for (int mi = 0; mi < 2; mi++) {
        int r0 = m0 + mi * 16 + g;
        #pragma unroll
        for (int ni = 0; ni < 16; ni++) {
            int c = ni * 8 + 2 * t;
            Ps[ r0      *APS + c    ] = to_tf32(s[mi][ni][0]);
            Ps[ r0      *APS + c + 1] = to_tf32(s[mi][ni][1]);
            Ps[(r0 + 8) *APS + c    ] = to_tf32(s[mi][ni][2]);
            Ps[(r0 + 8) *APS + c + 1] = to_tf32(s[mi][ni][3]);
        }
    }
    __syncwarp();

    float o[2][4][4] = {};
    #pragma unroll
    for (int kk = 0; kk < 128; kk += 8) {
        uint32_t afrag[2][4];
        #pragma unroll
        for (int mi = 0; mi < 2; mi++) {
            int r = m0 + mi * 16;
            afrag[mi][0] = __float_as_uint(Ps[(r + g    )*APS + kk + t    ]);
            afrag[mi][1] = __float_as_uint(Ps[(r + g + 8)*APS + kk + t    ]);
            afrag[mi][2] = __float_as_uint(Ps[(r + g    )*APS + kk + t + 4]);
            afrag[mi][3] = __float_as_uint(Ps[(r + g + 8)*APS + kk + t + 4]);
        }
        #pragma unroll
        for (int ni = 0; ni < 4; ni++) {
            int c = ni * 8;
            uint32_t b0 = __float_as_uint(VT[(c + g)*APS + kk + t    ]);
            uint32_t b1 = __float_as_uint(VT[(c + g)*APS + kk + t + 4]);
            mma8(o[0][ni], afrag[0], b0, b1);
            mma8(o[1][ni], afrag[1], b0, b1);
        }
    }

    #pragma unroll
    for (int mi = 0; mi < 2; mi++) {
        int r0 = m0 + mi * 16 + g;
        #pragma unroll
        for (int ni = 0; ni < 4; ni++) {
            int d = ni * 8 + 2 * t;
            *(float2*)(g_o + (size_t)(n*NP + r0    )*DD + h*32 + d) =
                make_float2(o[mi][ni][0]*inv[mi][0], o[mi][ni][1]*inv[mi][0]);
            *(float2*)(g_o + (size_t)(n*NP + r0 + 8)*DD + h*32 + d) =
                make_float2(o[mi][ni][2]*inv[mi][1], o[mi][ni][3]*inv[mi][1]);
        }
    }
}

// ---------------- mean over Np -----------------------------------------------
__global__ void k_mean()
{
    int n = blockIdx.x, d = threadIdx.x;
    float s = 0.f;
    for (int p = 0; p < NP; p++) s += g_Htemp[((size_t)n*NP + p)*DD + d];
    g_Hs[n*DD + d] = s * (1.f/128.f);
}

// ---------------- graph adjacency --------------------------------------------
__global__ void k_graph(const float* __restrict__ adj)
{
    __shared__ float k2s[CC*DK];
    __shared__ float Amat[CC*65];
    int b = blockIdx.x, c = threadIdx.x;
    for (int idx = c; idx < CC*DK; idx += 64) k2s[idx] = g_k2[(size_t)b*CC*DK + idx];
    __syncthreads();
    float qreg[DK];
    #pragma unroll
    for (int d = 0; d < DK; d++) qreg[d] = g_q2[(size_t)b*CC*DK + c*DK + d];
    for (int e = 0; e < CC; e++) {
        float a = 0.f;
        #pragma unroll
        for (int d = 0; d < DK; d++) a += qreg[d] * k2s[e*DK + d];
        Amat[c*65 + e] = tanhf(a * 0.125f) + adj[c*CC + e];
    }
    for (int e = 0; e < CC; e++) g_mask[(size_t)b*CC*CC + c*CC + e] = 0.f;
    for (int kk = 0; kk < 8; kk++) {
        float best = -INFINITY; int bi = 0;
        for (int e = 0; e < CC; e++) {
            float v = Amat[c*65 + e];
            if (v > best) { best = v; bi = e; }
        }
        if (bi != c && best != 0.f) g_mask[(size_t)b*CC*CC + c*CC + bi] = 1.f;
        Amat[c*65 + bi] = -INFINITY;
    }
}

// ============== GAT v2: tensor-core aggregation + fused snorm LN =============
#define XST 68
#define AST 68
#define OST 132
#define GU  8704          // 128*68
__global__ void __launch_bounds__(256)
k_gat(const float* __restrict__ attsrc, const float* __restrict__ attdst,
      const float* __restrict__ gbias, const float* __restrict__ sg,
      const float* __restrict__ sb, float* __restrict__ out)
{
    extern __shared__ float sm[];
    float* U   = sm;                 // XhT / Os union
    float* Awt = sm + GU;            // 64*68
    float* Asv = sm + GU + 4352;
    float* Adv = sm + GU + 4416;
    float* XhT = U;
    float* Os  = U;

    int b = blockIdx.x >> 7, p = blockIdx.x & 127;
    int tid = threadIdx.x, w = tid >> 5, lane = tid & 31;
    int wm = w >> 2, wn = w & 3;
    int g = lane >> 2, t4 = lane & 3;

    float mr0[8], mr1[8];
    #pragma unroll
    for (int i = 0; i < 8; i++) {
        int t = w*8 + i;
        mr0[i] = g_mask[(size_t)b*CC*CC + lane*CC + t];
        mr1[i] = g_mask[(size_t)b*CC*CC + (lane+32)*CC + t];
    }

    float acc[2][4][4] = {};
    for (int h = 0; h < HS; h++) {
        __syncthreads();
        for (int idx = tid; idx < CC*FF; idx += 256) {
            int s = idx >> 7, f = idx & 127;
            XhT[f*XST + s] = to_tf32(g_xh[(size_t)(((b*CC + s)*NP + p))*(HS*FF) + h*FF + f]);
        }
        __syncthreads();

        for (int s = w; s < CC; s += 8) {
            float vs = 0.f, vd = 0.f;
            #pragma unroll
            for (int j = 0; j < 4; j++) {
                int f = lane + 32*j;
                float xv = XhT[f*XST + s];
                vs += xv * attsrc[h*FF + f];
                vd += xv * attdst[h*FF + f];
            }
            #pragma unroll
            for (int o = 16; o; o >>= 1) {
                vs += __shfl_xor_sync(0xffffffffu, vs, o);
                vd += __shfl_xor_sync(0xffffffffu, vd, o);
            }
            if (lane == 0) { Asv[s] = vs; Adv[s] = vd; }
        }
        __syncthreads();

        #pragma unroll
        for (int i = 0; i < 8; i++) {
            int t = w*8 + i;
            float adt = Adv[t];
            float e0 = Asv[lane]      + adt; e0 = e0 > 0.f ? e0 : 0.2f*e0;
            float e1 = Asv[lane + 32] + adt; e1 = e1 > 0.f ? e1 : 0.2f*e1;
            float me = fmaxf(mr0[i] > 0.5f ? e0 : GAT_NEG, mr1[i] > 0.5f ? e1 : GAT_NEG);
            #pragma unroll
            for (int o = 16; o; o >>= 1) me = fmaxf(me, __shfl_xor_sync(0xffffffffu, me, o));
            float w0 = (mr0[i] > 0.5f) ? expf(e0 - me) : 0.f;
            float w1 = (mr1[i] > 0.5f) ? expf(e1 - me) : 0.f;
            float ws = w0 + w1;
            #pragma unroll
            for (int o = 16; o; o >>= 1) ws += __shfl_xor_sync(0xffffffffu, ws, o);
            float inv = ws > 0.f ? 1.f / ws : 0.f;
            Awt[t*AST + lane]      = to_tf32(w0 * inv);
            Awt[t*AST + lane + 32] = to_tf32(w1 * inv);
        }
        __syncthreads();

        #pragma unroll
        for (int kk = 0; kk < CC; kk += 8) {
            uint32_t afrag[2][4];
            #pragma unroll
            for (int mi = 0; mi < 2; mi++) {
                int r = wm * 32 + mi * 16;
                afrag[mi][0] = __float_as_uint(Awt[(r + g    )*AST + kk + t4    ]);
                afrag[mi][1] = __float_as_uint(Awt[(r + g + 8)*AST + kk + t4    ]);
                afrag[mi][2] = __float_as_uint(Awt[(r + g    )*AST + kk + t4 + 4]);
                afrag[mi][3] = __float_as_uint(Awt[(r + g + 8)*AST + kk + t4 + 4]);
            }
            #pragma unroll
            for (int ni = 0; ni < 4; ni++) {
                int c = wn * 32 + ni * 8;
                uint32_t b0 = __float_as_uint(XhT[(c + g)*XST + kk + t4    ]);
                uint32_t b1 = __float_as_uint(XhT[(c + g)*XST + kk + t4 + 4]);
                mma8(acc[0][ni], afrag[0], b0, b1);
                mma8(acc[1][ni], afrag[1], b0, b1);
            }
        }
    }

    __syncthreads();
    for (int idx = tid; idx < CC*DD; idx += 256) {
        int r = idx >> 7, f = idx & 127;
        Os[r*OST + f] = g_Htemp[(((size_t)(b*CC + r))*NP + p)*DD + f] + gbias[f];
    }
    __syncthreads();
    #pragma unroll
    for (int mi = 0; mi < 2; mi++)
        #pragma unroll
        for (int ni = 0; ni < 4; ni++) {
            int r = wm*32 + mi*16 + g;
            int c = wn*32 + ni*8 + 2*t4;
            #pragma unroll
            for (int half = 0; half < 2; half++) {
                int row = r + half*8;
                Os[row*OST + c    ] += acc[mi][ni][half*2 + 0] * 0.25f;
                Os[row*OST + c + 1] += acc[mi][ni][half*2 + 1] * 0.25f;
            }
        }
    __syncthreads();
    {
        float4 g4 = ((const float4*)sg)[lane];
        float4 b4 = ((const float4*)sb)[lane];
        for (int r = w; r < CC; r += 8) {
            float4 v = *(float4*)&Os[r*OST + lane*4];
            float s1 = v.x + v.y + v.z + v.w;
            #pragma unroll
            for (int o = 16; o; o >>= 1) s1 += __shfl_xor_sync(0xffffffffu, s1, o);
            float mean = s1 * (1.f/128.f);
            float dx=v.x-mean, dy=v.y-mean, dz=v.z-mean, dw=v.w-mean;
            float q = dx*dx+dy*dy+dz*dz+dw*dw;
            #pragma unroll
            for (int o = 16; o; o >>= 1) q += __shfl_xor_sync(0xffffffffu, q, o);
            float inv = rsqrtf(q * (1.f/128.f) + 1e-5f);
            float4 ov;
            ov.x = dx*inv*g4.x + b4.x; ov.y = dy*inv*g4.y + b4.y;
            ov.z = dz*inv*g4.z + b4.z; ov.w = dw*inv*g4.w + b4.w;
            ((float4*)(out + (((size_t)(b*CC + r))*NP + p)*DD))[lane] = ov;
        }
    }
}

// ---------------- host launch -------------------------------------------------
extern "C" void kernel_launch(void* const* d_in, const int* in_sizes, int n_in,
                              void* d_out, int out_size)
{
    const float* H_in      = (const float*)d_in[0];
    const float* static_adj= (const float*)d_in[1];
    const float* attn_in_w = (const float*)d_in[2];
    const float* attn_in_b = (const float*)d_in[3];
    const float* attn_out_w= (const float*)d_in[4];
    const float* attn_out_b= (const float*)d_in[5];
    const float* ln1_g     = (const float*)d_in[6];
    const float* ln1_b     = (const float*)d_in[7];
    const float* ln2_g     = (const float*)d_in[8];
    const float* ln2_b     = (const float*)d_in[9];
    const float* ff1_w     = (const float*)d_in[10];
    const float* ff1_b     = (const float*)d_in[11];
    const float* ff2_w     = (const float*)d_in[12];
    const float* ff2_b     = (const float*)d_in[13];
    const float* tnorm_g   = (const float*)d_in[14];
    const float* tnorm_b   = (const float*)d_in[15];
    const float* q_w       = (const float*)d_in[16];
    const float* q_b       = (const float*)d_in[17];
    const float* k_w       = (const float*)d_in[18];
    const float* k_b       = (const float*)d_in[19];
    const float* gat_w     = (const float*)d_in[20];
    const float* gat_att_src = (const float*)d_in[21];
    const float* gat_att_dst = (const float*)d_in[22];
    const float* gat_bias  = (const float*)d_in[23];
    const float* snorm_g   = (const float*)d_in[24];
    const float* snorm_b   = (const float*)d_in[25];

    float *h_, *qkv_, *o_, *x_, *ff_, *Htemp_, *xh_, *Hs_, *q2_, *k2_;
    cudaGetSymbolAddress((void**)&h_,     g_h);
    cudaGetSymbolAddress((void**)&qkv_,   g_qkv);
    cudaGetSymbolAddress((void**)&o_,     g_o);
    cudaGetSymbolAddress((void**)&x_,     g_x);
    cudaGetSymbolAddress((void**)&ff_,    g_ff);
    cudaGetSymbolAddress((void**)&Htemp_, g_Htemp);
    cudaGetSymbolAddress((void**)&xh_,    g_xh);
    cudaGetSymbolAddress((void**)&Hs_,    g_Hs);
    cudaGetSymbolAddress((void**)&q2_,    g_q2);
    cudaGetSymbolAddress((void**)&k2_,    g_k2);

    const int attn_smem = (128*APS + 32*APS) * 4;      // 84480
    const int gat_smem  = (GU + 4352 + 128) * 4;       // 52736
    cudaFuncSetAttribute(k_attn_mma, cudaFuncAttributeMaxDynamicSharedMemorySize, attn_smem);
    cudaFuncSetAttribute(k_gat,  cudaFuncAttributeMaxDynamicSharedMemorySize, gat_smem);

    // 1) h = ln1(x0)
    k_ln<<<NTOK/8, 256>>>(H_in, nullptr, ln1_g, ln1_b, h_);
    // 2) qkv = h @ Wqkv^T + b
    k_mma<<<dim3(3, NTOK/TBM), 256>>>(h_, attn_in_w, attn_in_b, nullptr, qkv_,
                                      NTOK, 384, 128, 0);
    // 3) temporal attention (tensor cores)
    k_attn_mma<<<NSEQ*HT, 128, attn_smem>>>();
    // 4) x1 = x0 + o @ Wout^T + b
    k_mma<<<dim3(1, NTOK/TBM), 256>>>(o_, attn_out_w, attn_out_b, H_in, x_,
                                      NTOK, 128, 128, 0);
    // 5) h = ln2(x1)
    k_ln<<<NTOK/8, 256>>>(x_, nullptr, ln2_g, ln2_b, h_);
    // 6) ff = relu(h @ W1^T + b1)
    k_mma<<<dim3(4, NTOK/TBM), 256>>>(h_, ff1_w, ff1_b, nullptr, ff_,
                                      NTOK, 512, 128, 1);
    // 7) x2 = x1 + ff @ W2^T + b2
    k_mma<<<dim3(1, NTOK/TBM), 256>>>(ff_, ff2_w, ff2_b, x_, x_,
                                      NTOK, 128, 512, 0);
    // 8) H_temp = ln(x0 + x2, tnorm)
    k_ln<<<NTOK/8, 256>>>(x_, H_in, tnorm_g, tnorm_b, Htemp_);
    // 9) xh = H_temp @ gat_w^T
    k_mma<<<dim3(4, NTOK/TBM), 256>>>(Htemp_, gat_w, nullptr, nullptr, xh_,
                                      NTOK, 512, 128, 0);
    // 10) Hs = mean_p(H_temp)
    k_mean<<<NSEQ, 128>>>();
    // 11) q2, k2
    k_gemm<<<dim3(1, NSEQ/BM), 256>>>(Hs_, q_w, q_b, q2_, NSEQ, 64, 128);
    k_gemm<<<dim3(1, NSEQ/BM), 256>>>(Hs_, k_w, k_b, k2_, NSEQ, 64, 128);
    // 12) adjacency / top-k / mask
    k_graph<<<BB, 64>>>(static_adj);
    // 13) GAT v2 (tensor cores) + snorm LN -> output
    k_gat<<<BB*NP, 256, gat_smem>>>(gat_att_src, gat_att_dst, gat_bias,
                                    snorm_g, snorm_b, (float*)d_out);
}

// round 7
// speedup vs baseline: 1.2387x; 1.0524x over previous
#include <cuda_runtime.h>
#include <cuda_bf16.h>
#include <math.h>
#include <stdint.h>

#define BB   16
#define CC   64
#define NP   128
#define DD   128
#define HT   4
#define DH   32
#define HS   4
#define FF   128
#define DK   64
#define NTOK (BB*CC*NP)      // 131072
#define NSEQ (BB*CC)         // 1024
#define GAT_NEG -1e30f

// ---------------- scratch ----------------------------------------------------
__device__ float g_h[NTOK*DD];
__device__ float g_qkv[(size_t)NTOK*3*DD];
__device__ float g_o[NTOK*DD];
__device__ float g_x[NTOK*DD];
__device__ float g_ff[(size_t)NTOK*4*DD];
__device__ float g_Htemp[NTOK*DD];
__device__ float g_xh[(size_t)NTOK*HS*FF];
__device__ float g_Hs[NSEQ*DD];
__device__ float g_q2[NSEQ*DK];
__device__ float g_k2[NSEQ*DK];
__device__ float g_mask[BB*CC*CC];
__device__ float g_watt[8*DD];             // rows 0-3: w_src[h], 4-7: w_dst[h]
__device__ float g_asrc[BB*HS*NP*CC];      // [b][h][p][s]
__device__ float g_adst[BB*HS*NP*CC];

// ---------------- helpers ----------------------------------------------------
__device__ __forceinline__ float to_tf32(float x) {
    asm("cvt.rna.tf32.f32 %0, %1;" : "=f"(x) : "f"(x));
    return x;
}
__device__ __forceinline__ void mma8(float c[4], const uint32_t a[4],
                                     uint32_t b0, uint32_t b1) {
    asm volatile(
        "mma.sync.aligned.m16n8k8.row.col.f32.tf32.tf32.f32 "
        "{%0,%1,%2,%3}, {%4,%5,%6,%7}, {%8,%9}, {%0,%1,%2,%3};"
        : "+f"(c[0]), "+f"(c[1]), "+f"(c[2]), "+f"(c[3])
        : "r"(a[0]), "r"(a[1]), "r"(a[2]), "r"(a[3]), "r"(b0), "r"(b1));
}
__device__ __forceinline__ void cp_async16(float* smem, const float* gmem) {
    uint32_t s = (uint32_t)__cvta_generic_to_shared(smem);
    asm volatile("cp.async.cg.shared.global [%0], [%1], 16;" :: "r"(s), "l"(gmem));
}

// ---------------- LayerNorm: warp per row, optional fused add ----------------
__global__ void k_ln(const float* __restrict__ x, const float* __restrict__ add,
                     const float* __restrict__ gw, const float* __restrict__ bw,
                     float* __restrict__ out)
{
    int row  = blockIdx.x * 8 + (threadIdx.x >> 5);
    int lane = threadIdx.x & 31;
    const float4* xp = (const float4*)(x + (size_t)row * DD);
    float4 v = xp[lane];
    if (add) {
        float4 a = ((const float4*)(add + (size_t)row * DD))[lane];
        v.x += a.x; v.y += a.y; v.z += a.z; v.w += a.w;
    }
    float s = v.x + v.y + v.z + v.w;
    #pragma unroll
    for (int o = 16; o; o >>= 1) s += __shfl_xor_sync(0xffffffffu, s, o);
    float mean = s * (1.f/128.f);
    float dx = v.x-mean, dy = v.y-mean, dz = v.z-mean, dw = v.w-mean;
    float q = dx*dx + dy*dy + dz*dz + dw*dw;
    #pragma unroll
    for (int o = 16; o; o >>= 1) q += __shfl_xor_sync(0xffffffffu, q, o);
    float inv = rsqrtf(q * (1.f/128.f) + 1e-5f);
    float4 g4 = ((const float4*)gw)[lane];
    float4 b4 = ((const float4*)bw)[lane];
    float4 o4;
    o4.x = dx*inv*g4.x + b4.x;  o4.y = dy*inv*g4.y + b4.y;
    o4.z = dz*inv*g4.z + b4.z;  o4.w = dw*inv*g4.w + b4.w;
    ((float4*)(out + (size_t)row * DD))[lane] = o4;
}

// ---------------- tf32 GEMM, cp.async 2-stage pipeline -----------------------
// smem: As[2][128][36] + Bs[2][128][36] dyn (73728 B)
#define TBM 128
#define TBN 128
#define TILE (128*36)
__global__ void __launch_bounds__(256)
k_mma(const float* __restrict__ A, const float* __restrict__ W,
      const float* __restrict__ bias, const float* __restrict__ res,
      float* __restrict__ out, int M, int N, int K, int relu)
{
    extern __shared__ float smbuf[];
    float* As = smbuf;             // [2][128][36]
    float* Bs = smbuf + 2*TILE;    // [2][128][36]
    int tid  = threadIdx.x;
    int warp = tid >> 5, lane = tid & 31;
    int wm = warp >> 1, wn = warp & 1;
    int g = lane >> 2, t = lane & 3;
    int m0 = blockIdx.y * TBM;
    int n0 = blockIdx.x * TBN;
    int lr = tid >> 3, lc = (tid & 7) << 2;   // 32 rows per pass, 4 passes cover 128

    float acc[2][8][4] = {};
    const int nk = K >> 5;

    // prefetch tile 0 -> buf 0
    #pragma unroll
    for (int i = 0; i < 4; i++) {
        int r = lr + i * 32;
        cp_async16(&As[r*36 + lc], A + (size_t)(m0 + r) * K + lc);
        cp_async16(&Bs[r*36 + lc], W + (size_t)(n0 + r) * K + lc);
    }
    asm volatile("cp.async.commit_group;");

    for (int kt = 0; kt < nk; kt++) {
        int buf = (kt & 1) * TILE;
        if (kt + 1 < nk) {
            int nb = ((kt + 1) & 1) * TILE;
            int ko = (kt + 1) << 5;
            #pragma unroll
            for (int i = 0; i < 4; i++) {
                int r = lr + i * 32;
                cp_async16(&As[nb + r*36 + lc], A + (size_t)(m0 + r) * K + ko + lc);
                cp_async16(&Bs[nb + r*36 + lc], W + (size_t)(n0 + r) * K + ko + lc);
            }
            asm volatile("cp.async.commit_group;");
            asm volatile("cp.async.wait_group 1;");
        } else {
            asm volatile("cp.async.wait_group 0;");
        }
        __syncthreads();
        #pragma unroll
        for (int kk = 0; kk < 32; kk += 8) {
            uint32_t afrag[2][4];
            #pragma unroll
            for (int mi = 0; mi < 2; mi++) {
                int r = wm * 32 + mi * 16;
                afrag[mi][0] = __float_as_uint(As[buf + (r + g    )*36 + kk + t    ]);
                afrag[mi][1] = __float_as_uint(As[buf + (r + g + 8)*36 + kk + t    ]);
                afrag[mi][2] = __float_as_uint(As[buf + (r + g    )*36 + kk + t + 4]);
                afrag[mi][3] = __float_as_uint(As[buf + (r + g + 8)*36 + kk + t + 4]);
            }
            #pragma unroll
            for (int ni = 0; ni < 8; ni++) {
                int c = wn * 64 + ni * 8;
                uint32_t b0 = __float_as_uint(Bs[buf + (c + g)*36 + kk + t    ]);
                uint32_t b1 = __float_as_uint(Bs[buf + (c + g)*36 + kk + t + 4]);
                mma8(acc[0][ni], afrag[0], b0, b1);
                mma8(acc[1][ni], afrag[1], b0, b1);
            }
        }
        __syncthreads();
    }

    #pragma unroll
    for (int mi = 0; mi < 2; mi++) {
        #pragma unroll
        for (int ni = 0; ni < 8; ni++) {
            int r = m0 + wm * 32 + mi * 16 + g;
            int c = n0 + wn * 64 + ni * 8 + 2 * t;
            float bv0 = bias ? bias[c]     : 0.f;
            float bv1 = bias ? bias[c + 1] : 0.f;
            #pragma unroll
            for (int half = 0; half < 2; half++) {
                int row = r + half * 8;
                float v0 = acc[mi][ni][half*2 + 0] + bv0;
                float v1 = acc[mi][ni][half*2 + 1] + bv1;
                if (relu) { v0 = fmaxf(v0, 0.f); v1 = fmaxf(v1, 0.f); }
                if (res) {
                    const float2 rr = *(const float2*)(res + (size_t)row * N + c);
                    v0 += rr.x; v1 += rr.y;
                }
                *(float2*)(out + (size_t)row * N + c) = make_float2(v0, v1);
            }
        }
    }
}

// ---------------- small SIMT GEMM (q2/k2) ------------------------------------
#define BM 64
#define BN 64
#define BK 16
__global__ void k_gemm(const float* __restrict__ A, const float* __restrict__ W,
                       const float* __restrict__ bias, float* __restrict__ out,
                       int M, int N, int K)
{
    __shared__ float As[BK][BM];
    __shared__ float Bs[BK][BN];
    int tid = threadIdx.x;
    int tx = tid & 15, ty = tid >> 4;
    int m0 = blockIdx.y * BM, n0 = blockIdx.x * BN;
    int lr = tid >> 2;
    int lk = (tid & 3) * 4;
    float acc[4][4] = {};
    for (int k0 = 0; k0 < K; k0 += BK) {
        float4 a4 = *(const float4*)(A + (size_t)(m0 + lr) * K + k0 + lk);
        float4 b4 = *(const float4*)(W + (size_t)(n0 + lr) * K + k0 + lk);
        As[lk+0][lr] = a4.x; As[lk+1][lr] = a4.y; As[lk+2][lr] = a4.z; As[lk+3][lr] = a4.w;
        Bs[lk+0][lr] = b4.x; Bs[lk+1][lr] = b4.y; Bs[lk+2][lr] = b4.z; Bs[lk+3][lr] = b4.w;
        __syncthreads();
        #pragma unroll
        for (int k = 0; k < BK; k++) {
            float4 ra = *(const float4*)&As[k][ty*4];
            float4 rb = *(const float4*)&Bs[k][tx*4];
            float av[4] = {ra.x, ra.y, ra.z, ra.w};
            float bv[4] = {rb.x, rb.y, rb.z, rb.w};
            #pragma unroll
            for (int i = 0; i < 4; i++)
                #pragma unroll
                for (int j = 0; j < 4; j++)
                    acc[i][j] += av[i] * bv[j];
        }
        __syncthreads();
    }
    #pragma unroll
    for (int i = 0; i < 4; i++) {
        int m = m0 + ty*4 + i;
        #pragma unroll
        for (int j = 0; j < 4; j++) {
            int n = n0 + tx*4 + j;
            out[(size_t)m * N + n] = acc[i][j] + bias[n];
        }
    }
}

// ============== tensor-core attention (R4-proven) ============================
#define AQS 36
#define APS 132
__global__ void __launch_bounds__(128)
k_attn_mma()
{
    extern __shared__ float sm[];
    float* U  = sm;
    float* VT = sm + 128*APS;
    float* Qs = U;
    float* Ks = U + 128*AQS;
    float* Ps = U;

    int n = blockIdx.x >> 2, h = blockIdx.x & 3;
    int tid = threadIdx.x;
    int warp = tid >> 5, lane = tid & 31;
    int g = lane >> 2, t = lane & 3;
    int m0 = warp * 32;
    const float* base = g_qkv + (size_t)n * NP * 3 * DD;

    for (int idx = tid; idx < NP*DH; idx += 128) {
        int j = idx >> 5, d = idx & 31;
        Qs[j*AQS + d]  = base[j*384 +       h*32 + d];
        Ks[j*AQS + d]  = base[j*384 + 128 + h*32 + d];
        VT[d*APS + j]  = base[j*384 + 256 + h*32 + d];
    }
    __syncthreads();

    float s[2][16][4] = {};
    #pragma unroll
    for (int kk = 0; kk < 32; kk += 8) {
        uint32_t afrag[2][4];
        #pragma unroll
        for (int mi = 0; mi < 2; mi++) {
            int r = m0 + mi * 16;
            afrag[mi][0] = __float_as_uint(Qs[(r + g    )*AQS + kk + t    ]);
            afrag[mi][1] = __float_as_uint(Qs[(r + g + 8)*AQS + kk + t    ]);
            afrag[mi][2] = __float_as_uint(Qs[(r + g    )*AQS + kk + t + 4]);
            afrag[mi][3] = __float_as_uint(Qs[(r + g + 8)*AQS + kk + t + 4]);
        }
        #pragma unroll
        for (int ni = 0; ni < 16; ni++) {
            int c = ni * 8;
            uint32_t b0 = __float_as_uint(Ks[(c + g)*AQS + kk + t    ]);
            uint32_t b1 = __float_as_uint(Ks[(c + g)*AQS + kk + t + 4]);
            mma8(s[0][ni], afrag[0], b0, b1);
            mma8(s[1][ni], afrag[1], b0, b1);
        }
    }
    __syncthreads();

    const float scale = 0.17677669529663687f;
    float mx[2][2] = {{-INFINITY,-INFINITY},{-INFINITY,-INFINITY}};
    #pragma unroll
    for (int mi = 0; mi < 2; mi++)
        #pragma unroll
        for (int ni = 0; ni < 16; ni++) {
            #pragma unroll
            for (int q = 0; q < 4; q++) s[mi][ni][q] *= scale;
            mx[mi][0] = fmaxf(mx[mi][0], fmaxf(s[mi][ni][0], s[mi][ni][1]));
            mx[mi][1] = fmaxf(mx[mi][1], fmaxf(s[mi][ni][2], s[mi][ni][3]));
        }
    #pragma unroll
    for (int mi = 0; mi < 2; mi++)
        #pragma unroll
        for (int hf = 0; hf < 2; hf++) {
            mx[mi][hf] = fmaxf(mx[mi][hf], __shfl_xor_sync(0xffffffffu, mx[mi][hf], 1));
            mx[mi][hf] = fmaxf(mx[mi][hf], __shfl_xor_sync(0xffffffffu, mx[mi][hf], 2));
        }
    float sum[2][2] = {};
    #pragma unroll
    for (int mi = 0; mi < 2; mi++)
        #pragma unroll
        for (int ni = 0; ni < 16; ni++) {
            s[mi][ni][0] = expf(s[mi][ni][0] - mx[mi][0]);
            s[mi][ni][1] = expf(s[mi][ni][1] - mx[mi][0]);
            s[mi][ni][2] = expf(s[mi][ni][2] - mx[mi][1]);
            s[mi][ni][3] = expf(s[mi][ni][3] - mx[mi][1]);
            sum[mi][0] += s[mi][ni][0] + s[mi][ni][1];
            sum[mi][1] += s[mi][ni][2] + s[mi][ni][3];
        }
    float inv[2][2];
    #pragma unroll
    for (int mi = 0; mi < 2; mi++)
        #pragma unroll
        for (int hf = 0; hf < 2; hf++) {
            float ss = sum[mi][hf];
            ss += __shfl_xor_sync(0xffffffffu, ss, 1);
            ss += __shfl_xor_sync(0xffffffffu, ss, 2);
            inv[mi][hf] = 1.f / ss;
        }

    #pragma unroll
    for (int mi = 0; mi < 2; mi++) {
        int r0 = m0 + mi * 16 + g;
        #pragma unroll
        for (int ni = 0; ni < 16; ni++) {
            int c = ni * 8 + 2 * t;
            Ps[ r0      *APS + c    ] = s[mi][ni][0];
            Ps[ r0      *APS + c + 1] = s[mi][ni][1];
            Ps[(r0 + 8) *APS + c    ] = s[mi][ni][2];
            Ps[(r0 + 8) *APS + c + 1] = s[mi][ni][3];
        }
    }
    __syncwarp();

    float o[2][4][4] = {};
    #pragma unroll
    for (int kk = 0; kk < 128; kk += 8) {
        uint32_t afrag[2][4];
        #pragma unroll
        for (int mi = 0; mi < 2; mi++) {
            int r = m0 + mi * 16;
            afrag[mi][0] = __float_as_uint(Ps[(r + g    )*APS + kk + t    ]);
            afrag[mi][1] = __float_as_uint(Ps[(r + g + 8)*APS + kk + t    ]);
            afrag[mi][2] = __float_as_uint(Ps[(r + g    )*APS + kk + t + 4]);
            afrag[mi][3] = __float_as_uint(Ps[(r + g + 8)*APS + kk + t + 4]);
        }
        #pragma unroll
        for (int ni = 0; ni < 4; ni++) {
            int c = ni * 8;
            uint32_t b0 = __float_as_uint(VT[(c + g)*APS + kk + t    ]);
            uint32_t b1 = __float_as_uint(VT[(c + g)*APS + kk + t + 4]);
            mma8(o[0][ni], afrag[0], b0, b1);
            mma8(o[1][ni], afrag[1], b0, b1);
        }
    }

    #pragma unroll
    for (int mi = 0; mi < 2; mi++) {
        int r0 = m0 + mi * 16 + g;
        #pragma unroll
        for (int ni = 0; ni < 4; ni++) {
            int d = ni * 8 + 2 * t;
            *(float2*)(g_o + (size_t)(n*NP + r0    )*DD + h*32 + d) =
                make_float2(o[mi][ni][0]*inv[mi][0], o[mi][ni][1]*inv[mi][0]);
            *(float2*)(g_o + (size_t)(n*NP + r0 + 8)*DD + h*32 + d) =
                make_float2(o[mi][ni][2]*inv[mi][1], o[mi][ni][3]*inv[mi][1]);
        }
    }
}

// ---------------- mean over Np -----------------------------------------------
__global__ void k_mean()
{
    int n = blockIdx.x, d = threadIdx.x;
    float s = 0.f;
    for (int p = 0; p < NP; p++) s += g_Htemp[((size_t)n*NP + p)*DD + d];
    g_Hs[n*DD + d] = s * (1.f/128.f);
}

// ---------------- W_att = gat_w[h]^T @ att{src,dst}[h] -----------------------
__global__ void k_watt(const float* __restrict__ gw, const float* __restrict__ asv,
                       const float* __restrict__ adv)
{
    int idx = blockIdx.x * 256 + threadIdx.x;   // 1024 total
    int r = idx >> 7, d = idx & 127;
    int h = r & 3;
    const float* att = (r < 4) ? asv : adv;
    float s = 0.f;
    for (int f = 0; f < 128; f++)
        s += att[h*FF + f] * gw[h*FF*DD + f*DD + d];
    g_watt[r*DD + d] = s;
}

// ---------------- asrc/adst = H_temp @ W_att^T, scattered layout -------------
__global__ void k_asd()
{
    __shared__ float4 W4[8][32];
    int tid = threadIdx.x, warp = tid >> 5, lane = tid & 31;
    for (int i = tid; i < 256; i += 256)
        ((float4*)W4)[i] = ((const float4*)g_watt)[i];
    __syncthreads();
    int tok = blockIdx.x * 8 + warp;
    float4 v = ((const float4*)(g_Htemp + (size_t)tok * DD))[lane];
    int p = tok & 127, bs = tok >> 7;
    int s = bs & 63, b = bs >> 6;
    #pragma unroll
    for (int r = 0; r < 8; r++) {
        float4 w = W4[r][lane];
        float a = v.x*w.x + v.y*w.y + v.z*w.z + v.w*w.w;
        #pragma unroll
        for (int o = 16; o; o >>= 1) a += __shfl_xor_sync(0xffffffffu, a, o);
        if (lane == 0) {
            int h = r & 3;
            float* dst = (r < 4) ? g_asrc : g_adst;
            dst[(((b*4 + h)*128 + p)*64) + s] = a;
        }
    }
}

// ---------------- graph adjacency --------------------------------------------
__global__ void k_graph(const float* __restrict__ adj)
{
    __shared__ float k2s[CC*DK];
    __shared__ float Amat[CC*65];
    int b = blockIdx.x, c = threadIdx.x;
    for (int idx = c; idx < CC*DK; idx += 64) k2s[idx] = g_k2[(size_t)b*CC*DK + idx];
    __syncthreads();
    float qreg[DK];
    #pragma unroll
    for (int d = 0; d < DK; d++) qreg[d] = g_q2[(size_t)b*CC*DK + c*DK + d];
    for (int e = 0; e < CC; e++) {
        float a = 0.f;
        #pragma unroll
        for (int d = 0; d < DK; d++) a += qreg[d] * k2s[e*DK + d];
        Amat[c*65 + e] = tanhf(a * 0.125f) + adj[c*CC + e];
    }
    for (int e = 0; e < CC; e++) g_mask[(size_t)b*CC*CC + c*CC + e] = 0.f;
    for (int kk = 0; kk < 8; kk++) {
        float best = -INFINITY; int bi = 0;
        for (int e = 0; e < CC; e++) {
            float v = Amat[c*65 + e];
            if (v > best) { best = v; bi = e; }
        }
        if (bi != c && best != 0.f) g_mask[(size_t)b*CC*CC + c*CC + bi] = 1.f;
        Amat[c*65 + bi] = -INFINITY;
    }
}

// ============== GAT v2: tensor-core aggregation + fused snorm LN =============
#define XST 68
#define AST 68
#define OST 132
#define GU  8704          // 128*68
__global__ void __launch_bounds__(256)
k_gat(const float* __restrict__ gbias, const float* __restrict__ sg,
      const float* __restrict__ sb, float* __restrict__ out)
{
    extern __shared__ float sm[];
    float* U   = sm;                 // XhT / Os union
    float* Awt = sm + GU;            // 64*68
    float* Asv = sm + GU + 4352;
    float* Adv = sm + GU + 4416;
    float* XhT = U;
    float* Os  = U;

    int b = blockIdx.x >> 7, p = blockIdx.x & 127;
    int tid = threadIdx.x, w = tid >> 5, lane = tid & 31;
    int wm = w >> 2, wn = w & 3;
    int g = lane >> 2, t4 = lane & 3;

    float mr0[8], mr1[8];
    #pragma unroll
    for (int i = 0; i < 8; i++) {
        int t = w*8 + i;
        mr0[i] = g_mask[(size_t)b*CC*CC + lane*CC + t];
        mr1[i] = g_mask[(size_t)b*CC*CC + (lane+32)*CC + t];
    }

    float acc[2][4][4] = {};
    for (int h = 0; h < HS; h++) {
        __syncthreads();
        for (int idx = tid; idx < CC*FF; idx += 256) {
            int s = idx >> 7, f = idx & 127;
            XhT[f*XST + s] = g_xh[(size_t)(((b*CC + s)*NP + p))*(HS*FF) + h*FF + f];
        }
        if (tid < 64)            Asv[tid]      = g_asrc[(((b*4 + h)*128 + p)*64) + tid];
        else if (tid < 128)      Adv[tid - 64] = g_adst[(((b*4 + h)*128 + p)*64) + tid - 64];
        __syncthreads();

        #pragma unroll
        for (int i = 0; i < 8; i++) {
            int t = w*8 + i;
            float adt = Adv[t];
            float e0 = Asv[lane]      + adt; e0 = e0 > 0.f ? e0 : 0.2f*e0;
            float e1 = Asv[lane + 32] + adt; e1 = e1 > 0.f ? e1 : 0.2f*e1;
            float me = fmaxf(mr0[i] > 0.5f ? e0 : GAT_NEG, mr1[i] > 0.5f ? e1 : GAT_NEG);
            #pragma unroll
            for (int o = 16; o; o >>= 1) me = fmaxf(me, __shfl_xor_sync(0xffffffffu, me, o));
            float w0 = (mr0[i] > 0.5f) ? expf(e0 - me) : 0.f;
            float w1 = (mr1[i] > 0.5f) ? expf(e1 - me) : 0.f;
            float ws = w0 + w1;
            #pragma unroll
            for (int o = 16; o; o >>= 1) ws += __shfl_xor_sync(0xffffffffu, ws, o);
            float inv = ws > 0.f ? 1.f / ws : 0.f;
            Awt[t*AST + lane]      = w0 * inv;
            Awt[t*AST + lane + 32] = w1 * inv;
        }
        __syncthreads();

        #pragma unroll
        for (int kk = 0; kk < CC; kk += 8) {
            uint32_t afrag[2][4];
            #pragma unroll
            for (int mi = 0; mi < 2; mi++) {
                int r = wm * 32 + mi * 16;
                afrag[mi][0] = __float_as_uint(Awt[(r + g    )*AST + kk + t4    ]);
                afrag[mi][1] = __float_as_uint(Awt[(r + g + 8)*AST + kk + t4    ]);
                afrag[mi][2] = __float_as_uint(Awt[(r + g    )*AST + kk + t4 + 4]);
                afrag[mi][3] = __float_as_uint(Awt[(r + g + 8)*AST + kk + t4 + 4]);
            }
            #pragma unroll
            for (int ni = 0; ni < 4; ni++) {
                int c = wn * 32 + ni * 8;
                uint32_t b0 = __float_as_uint(XhT[(c + g)*XST + kk + t4    ]);
                uint32_t b1 = __float_as_uint(XhT[(c + g)*XST + kk + t4 + 4]);
                mma8(acc[0][ni], afrag[0], b0, b1);
                mma8(acc[1][ni], afrag[1], b0, b1);
            }
        }
    }

    __syncthreads();
    for (int idx = tid; idx < CC*DD; idx += 256) {
        int r = idx >> 7, f = idx & 127;
        Os[r*OST + f] = g_Htemp[(((size_t)(b*CC + r))*NP + p)*DD + f] + gbias[f];
    }
    __syncthreads();
    #pragma unroll
    for (int mi = 0; mi < 2; mi++)
        #pragma unroll
        for (int ni = 0; ni < 4; ni++) {
            int r = wm*32 + mi*16 + g;
            int c = wn*32 + ni*8 + 2*t4;
            #pragma unroll
            for (int half = 0; half < 2; half++) {
                int row = r + half*8;
                Os[row*OST + c    ] += acc[mi][ni][half*2 + 0] * 0.25f;
                Os[row*OST + c + 1] += acc[mi][ni][half*2 + 1] * 0.25f;
            }
        }
    __syncthreads();
    {
        float4 g4 = ((const float4*)sg)[lane];
        float4 b4 = ((const float4*)sb)[lane];
        for (int r = w; r < CC; r += 8) {
            float4 v = *(float4*)&Os[r*OST + lane*4];
            float s1 = v.x + v.y + v.z + v.w;
            #pragma unroll
            for (int o = 16; o; o >>= 1) s1 += __shfl_xor_sync(0xffffffffu, s1, o);
            float mean = s1 * (1.f/128.f);
            float dx=v.x-mean, dy=v.y-mean, dz=v.z-mean, dw=v.w-mean;
            float q = dx*dx+dy*dy+dz*dz+dw*dw;
            #pragma unroll
            for (int o = 16; o; o >>= 1) q += __shfl_xor_sync(0xffffffffu, q, o);
            float inv = rsqrtf(q * (1.f/128.f) + 1e-5f);
            float4 ov;
            ov.x = dx*inv*g4.x + b4.x; ov.y = dy*inv*g4.y + b4.y;
            ov.z = dz*inv*g4.z + b4.z; ov.w = dw*inv*g4.w + b4.w;
            ((float4*)(out + (((size_t)(b*CC + r))*NP + p)*DD))[lane] = ov;
        }
    }
}

// ---------------- host launch -------------------------------------------------
extern "C" void kernel_launch(void* const* d_in, const int* in_sizes, int n_in,
                              void* d_out, int out_size)
{
    const float* H_in      = (const float*)d_in[0];
    const float* static_adj= (const float*)d_in[1];
    const float* attn_in_w = (const float*)d_in[2];
    const float* attn_in_b = (const float*)d_in[3];
    const float* attn_out_w= (const float*)d_in[4];
    const float* attn_out_b= (const float*)d_in[5];
    const float* ln1_g     = (const float*)d_in[6];
    const float* ln1_b     = (const float*)d_in[7];
    const float* ln2_g     = (const float*)d_in[8];
    const float* ln2_b     = (const float*)d_in[9];
    const float* ff1_w     = (const float*)d_in[10];
    const float* ff1_b     = (const float*)d_in[11];
    const float* ff2_w     = (const float*)d_in[12];
    const float* ff2_b     = (const float*)d_in[13];
    const float* tnorm_g   = (const float*)d_in[14];
    const float* tnorm_b   = (const float*)d_in[15];
    const float* q_w       = (const float*)d_in[16];
    const float* q_b       = (const float*)d_in[17];
    const float* k_w       = (const float*)d_in[18];
    const float* k_b       = (const float*)d_in[19];
    const float* gat_w     = (const float*)d_in[20];
    const float* gat_att_src = (const float*)d_in[21];
    const float* gat_att_dst = (const float*)d_in[22];
    const float* gat_bias  = (const float*)d_in[23];
    const float* snorm_g   = (const float*)d_in[24];
    const float* snorm_b   = (const float*)d_in[25];

    float *h_, *qkv_, *o_, *x_, *ff_, *Htemp_, *xh_, *Hs_, *q2_, *k2_;
    cudaGetSymbolAddress((void**)&h_,     g_h);
    cudaGetSymbolAddress((void**)&qkv_,   g_qkv);
    cudaGetSymbolAddress((void**)&o_,     g_o);
    cudaGetSymbolAddress((void**)&x_,     g_x);
    cudaGetSymbolAddress((void**)&ff_,    g_ff);
    cudaGetSymbolAddress((void**)&Htemp_, g_Htemp);
    cudaGetSymbolAddress((void**)&xh_,    g_xh);
    cudaGetSymbolAddress((void**)&Hs_,    g_Hs);
    cudaGetSymbolAddress((void**)&q2_,    g_q2);
    cudaGetSymbolAddress((void**)&k2_,    g_k2);

    const int mma_smem  = 4 * TILE * 4;                // 73728
    const int attn_smem = (128*APS + 32*APS) * 4;      // 84480
    const int gat_smem  = (GU + 4352 + 128) * 4;       // 52736
    cudaFuncSetAttribute(k_mma, cudaFuncAttributeMaxDynamicSharedMemorySize, mma_smem);
    cudaFuncSetAttribute(k_attn_mma, cudaFuncAttributeMaxDynamicSharedMemorySize, attn_smem);
    cudaFuncSetAttribute(k_gat,  cudaFuncAttributeMaxDynamicSharedMemorySize, gat_smem);

    // 0) W_att vectors (independent of data path)
    k_watt<<<4, 256>>>(gat_w, gat_att_src, gat_att_dst);
    // 1) h = ln1(x0)
    k_ln<<<NTOK/8, 256>>>(H_in, nullptr, ln1_g, ln1_b, h_);
    // 2) qkv = h @ Wqkv^T + b
    k_mma<<<dim3(3, NTOK/TBM), 256, mma_smem>>>(h_, attn_in_w, attn_in_b, nullptr, qkv_,
                                                NTOK, 384, 128, 0);
    // 3) temporal attention (tensor cores)
    k_attn_mma<<<NSEQ*HT, 128, attn_smem>>>();
    // 4) x1 = x0 + o @ Wout^T + b
    k_mma<<<dim3(1, NTOK/TBM), 256, mma_smem>>>(o_, attn_out_w, attn_out_b, H_in, x_,
                                                NTOK, 128, 128, 0);
    // 5) h = ln2(x1)
    k_ln<<<NTOK/8, 256>>>(x_, nullptr, ln2_g, ln2_b, h_);
    // 6) ff = relu(h @ W1^T + b1)
    k_mma<<<dim3(4, NTOK/TBM), 256, mma_smem>>>(h_, ff1_w, ff1_b, nullptr, ff_,
                                                NTOK, 512, 128, 1);
    // 7) x2 = x1 + ff @ W2^T + b2
    k_mma<<<dim3(1, NTOK/TBM), 256, mma_smem>>>(ff_, ff2_w, ff2_b, x_, x_,
                                                NTOK, 128, 512, 0);
    // 8) H_temp = ln(x0 + x2, tnorm)
    k_ln<<<NTOK/8, 256>>>(x_, H_in, tnorm_g, tnorm_b, Htemp_);
    // 9) xh = H_temp @ gat_w^T
    k_mma<<<dim3(4, NTOK/TBM), 256, mma_smem>>>(Htemp_, gat_w, nullptr, nullptr, xh_,
                                                NTOK, 512, 128, 0);
    // 10) asrc/adst from H_temp
    k_asd<<<NTOK/8, 256>>>();
    // 11) Hs = mean_p(H_temp)
    k_mean<<<NSEQ, 128>>>();
    // 12) q2, k2
    k_gemm<<<dim3(1, NSEQ/BM), 256>>>(Hs_, q_w, q_b, q2_, NSEQ, 64, 128);
    k_gemm<<<dim3(1, NSEQ/BM), 256>>>(Hs_, k_w, k_b, k2_, NSEQ, 64, 128);
    // 13) adjacency / top-k / mask
    k_graph<<<BB, 64>>>(static_adj);
    // 14) GAT v2 + snorm LN -> output
    k_gat<<<BB*NP, 256, gat_smem>>>(gat_bias, snorm_g, snorm_b, (float*)d_out);
}